// round 13
// baseline (speedup 1.0000x reference)
#include <cuda_runtime.h>
#include <cuda_fp16.h>
#include <math.h>
#include <stdint.h>

// Problem constants
constexpr int B_ = 4, L_ = 2048, D_ = 1024, H_ = 16, HD_ = 64;
constexpr int M_ = B_ * L_;
constexpr int WINDOW_ = 128;
constexpr size_t HSZ = (size_t)B_ * H_ * L_ * HD_;

// GEMM tiling (R9 config — proven fastest)
constexpr int TM = 128, TN = 128, KS = 64;
constexpr int NK2 = D_ / KS;
constexpr int ROWB = 144;
constexpr int TILE_B = 128 * ROWB;
constexpr int STAGE_B = 2 * TILE_B;
constexpr int NSTG = 3;
constexpr int GSMEM = NSTG * STAGE_B;       // 110592

// Attention tiling: AQ=128 queries, 256-key window, streaming online softmax
constexpr int AQ = 128;
constexpr int ANK = 256;
constexpr int ASTR = 144;
constexpr int OFF_Q = 0;
constexpr int OFF_K = OFF_Q + AQ * ASTR;    // 18432
constexpr int OFF_V = OFF_K + ANK * ASTR;   // 55296
constexpr int ASMEM = OFF_V + ANK * ASTR;   // 92160

// Scratch (device globals)
__device__ __half g_QKVh[3 * HSZ];
__device__ __half g_Sh[(size_t)M_ * D_];
__device__ __half g_Xh[(size_t)M_ * D_];
__device__ __half g_Wh[4ull * D_ * D_];
__device__ float g_cos[L_ * 32];
__device__ float g_sin[L_ * 32];

__device__ __forceinline__ uint32_t smem_u32(const void* p) {
    uint32_t a;
    asm("{ .reg .u64 t; cvta.to.shared.u64 t, %1; cvt.u32.u64 %0, t; }" : "=r"(a) : "l"(p));
    return a;
}

#define LDSM4(r, addr) \
    asm volatile("ldmatrix.sync.aligned.m8n8.x4.shared.b16 {%0,%1,%2,%3}, [%4];" \
                 : "=r"((r)[0]), "=r"((r)[1]), "=r"((r)[2]), "=r"((r)[3]) : "r"(addr))

#define LDSM4T(r, addr) \
    asm volatile("ldmatrix.sync.aligned.m8n8.x4.trans.shared.b16 {%0,%1,%2,%3}, [%4];" \
                 : "=r"((r)[0]), "=r"((r)[1]), "=r"((r)[2]), "=r"((r)[3]) : "r"(addr))

#define MMAH(d, a, b0, b1) \
    asm volatile("mma.sync.aligned.m16n8k16.row.col.f32.f16.f16.f32 " \
                 "{%0,%1,%2,%3}, {%4,%5,%6,%7}, {%8,%9}, {%0,%1,%2,%3};" \
                 : "+f"((d)[0]), "+f"((d)[1]), "+f"((d)[2]), "+f"((d)[3]) \
                 : "r"((a)[0]), "r"((a)[1]), "r"((a)[2]), "r"((a)[3]), "r"(b0), "r"(b1))

#define CP_WAIT(n) asm volatile("cp.async.wait_group %0;" :: "n"(n) : "memory")

__device__ __forceinline__ void cp16(uint32_t sa, const void* g) {
    asm volatile("cp.async.cg.shared.global [%0], [%1], 16;" :: "r"(sa), "l"(g));
}

__device__ __forceinline__ uint32_t pack_h2(float lo, float hi) {
    __half2 h = __floats2half2_rn(lo, hi);
    return *(uint32_t*)&h;
}

// Stage one 64-wide K-chunk given precomputed smem base address.
__device__ __forceinline__ void cp_stage(uint32_t sb, const __half* a, const __half* wt,
                                         int ko, int tid) {
    const __half* gp[2] = {a, wt};
#pragma unroll
    for (int t = 0; t < 2; t++) {
#pragma unroll
        for (int rep = 0; rep < 4; rep++) {
            const int c = rep * 256 + tid;
            const int row = c >> 3, ch = c & 7;
            cp16(sb + t * TILE_B + row * ROWB + ch * 16,
                 gp[t] + (size_t)row * D_ + ko + ch * 8);
        }
    }
    asm volatile("cp.async.commit_group;" ::: "memory");
}

// ---------------------------------------------------------------------------
// Single-pass fp16 GEMM with register-level A/B fragment double buffering.
// Stage bases precomputed; rotating stage index (no modulo in loop).
// ---------------------------------------------------------------------------
template <int MODE>
__global__ void __launch_bounds__(256, 2) gemm_mma(const __half* __restrict__ A,
                                                   const __half* __restrict__ Wh,
                                                   void* __restrict__ outv) {
    extern __shared__ char sm[];
    const int tid = threadIdx.x;
    const int lane = tid & 31, wid = tid >> 5;
    const int mw = wid & 1, nw = wid >> 1;
    const int r0 = blockIdx.y * TM, n0 = blockIdx.x * TN;
    const int z = blockIdx.z;

    const __half* A_t = A + (size_t)r0 * D_;
    const __half* W_t = Wh + (size_t)z * D_ * D_ + (size_t)n0 * D_;

    float acc[4][4][4];
#pragma unroll
    for (int i = 0; i < 4; i++)
#pragma unroll
        for (int j = 0; j < 4; j++)
#pragma unroll
            for (int k = 0; k < 4; k++) acc[i][j][k] = 0.f;

    const uint32_t smbase = smem_u32(sm);
    uint32_t sbase[NSTG];
#pragma unroll
    for (int s = 0; s < NSTG; s++) sbase[s] = smbase + s * STAGE_B;

    cp_stage(sbase[0], A_t, W_t, 0 * KS, tid);
    cp_stage(sbase[1], A_t, W_t, 1 * KS, tid);

    const uint32_t lrow = (lane & 15);
    const uint32_t lh = (lane >> 4) * 16;
    const uint32_t arow = (mw * 64 + lrow) * ROWB + lh;
    const uint32_t brow = (nw * 32 + lrow) * ROWB + lh;

    int scur = 0, spre = 2;   // current compute stage; stage to prefetch into
    for (int kc = 0; kc < NK2; kc++) {
        if (kc + 1 < NK2) { CP_WAIT(1); } else { CP_WAIT(0); }
        __syncthreads();

        const uint32_t sb = sbase[scur];
        uint32_t Bb[2][2][4];
        uint32_t Ab[2][4];
        LDSM4(Bb[0][0], sb + TILE_B + brow);
        LDSM4(Bb[0][1], sb + TILE_B + brow + 16 * ROWB);
        LDSM4(Ab[0], sb + arow);

        if (kc + 2 < NK2)
            cp_stage(sbase[spre], A_t, W_t, (kc + 2) * KS, tid);
        scur = (scur == NSTG - 1) ? 0 : scur + 1;
        spre = (spre == NSTG - 1) ? 0 : spre + 1;

#pragma unroll
        for (int kt = 0; kt < 4; kt++) {
            const int bc = kt & 1;
            if (kt < 3) {
                LDSM4(Bb[bc ^ 1][0], sb + TILE_B + brow + (kt + 1) * 32);
                LDSM4(Bb[bc ^ 1][1], sb + TILE_B + brow + 16 * ROWB + (kt + 1) * 32);
            }
#pragma unroll
            for (int mt = 0; mt < 4; mt++) {
                const int ac = mt & 1;
                if (mt < 3) {
                    LDSM4(Ab[ac ^ 1], sb + arow + (mt + 1) * 16 * ROWB + kt * 32);
                } else if (kt < 3) {
                    LDSM4(Ab[ac ^ 1], sb + arow + (kt + 1) * 32);
                }
#pragma unroll
                for (int nt = 0; nt < 4; nt++)
                    MMAH(acc[mt][nt], Ab[ac],
                         Bb[bc][nt >> 1][nt & 1], Bb[bc][nt >> 1][(nt & 1) + 2]);
            }
        }
    }

#pragma unroll
    for (int mt = 0; mt < 4; mt++) {
#pragma unroll
        for (int nt = 0; nt < 4; nt++) {
            const int row = r0 + mw * 64 + mt * 16 + (lane >> 2);
            const int col = n0 + nw * 32 + nt * 8 + 2 * (lane & 3);
            if (MODE == 1) {
                __half* out = (__half*)outv + (size_t)z * HSZ;
                const int h = col >> 6, dd = col & 63;
                const int bb0 = row >> 11, l0 = row & (L_ - 1);
                const int r8 = row + 8;
                const int bb1 = r8 >> 11, l1 = r8 & (L_ - 1);
                *(__half2*)(out + (((size_t)bb0 * H_ + h) * L_ + l0) * HD_ + dd) =
                    __floats2half2_rn(acc[mt][nt][0], acc[mt][nt][1]);
                *(__half2*)(out + (((size_t)bb1 * H_ + h) * L_ + l1) * HD_ + dd) =
                    __floats2half2_rn(acc[mt][nt][2], acc[mt][nt][3]);
            } else {
                float* out = (float*)outv;
                *(float2*)(out + (size_t)row * D_ + col) =
                    make_float2(acc[mt][nt][0], acc[mt][nt][1]);
                *(float2*)(out + (size_t)(row + 8) * D_ + col) =
                    make_float2(acc[mt][nt][2], acc[mt][nt][3]);
            }
        }
    }
}

// ---------------------------------------------------------------------------
// Fused prep: X->fp16, W0..W3->fp16, RoPE table. 2 elements per thread.
// ---------------------------------------------------------------------------
constexpr int XN4 = M_ * D_ / 4;
constexpr int WN4 = D_ * D_ / 4;
constexpr int PREP_N = XN4 + 4 * WN4 + L_ * 32;
constexpr int PREP_HALF = (PREP_N + 1) / 2;

__device__ __forceinline__ void prep_one(int i, const float4* __restrict__ X,
                                         const float4* __restrict__ W0,
                                         const float4* __restrict__ W1,
                                         const float4* __restrict__ W2,
                                         const float4* __restrict__ W3) {
    if (i < XN4) {
        const float4 v = X[i];
        __half2* o = (__half2*)g_Xh;
        o[2 * i]     = __floats2half2_rn(v.x, v.y);
        o[2 * i + 1] = __floats2half2_rn(v.z, v.w);
    } else if (i < XN4 + 4 * WN4) {
        const int widx = i - XN4;
        const int wi = widx >> 18, off = widx & (WN4 - 1);
        const float4* Wp = (wi == 0) ? W0 : (wi == 1) ? W1 : (wi == 2) ? W2 : W3;
        const float4 v = Wp[off];
        __half2* o = (__half2*)(g_Wh + (size_t)wi * D_ * D_);
        o[2 * off]     = __floats2half2_rn(v.x, v.y);
        o[2 * off + 1] = __floats2half2_rn(v.z, v.w);
    } else {
        const int r = i - XN4 - 4 * WN4;
        if (r < L_ * 32) {
            const int j = r & 31, l = r >> 5;
            const float invf = expf(-(float)j * 0.28782313662425575f);
            float s, c;
            sincosf((float)l * invf, &s, &c);
            g_cos[r] = c;
            g_sin[r] = s;
        }
    }
}

__global__ void prep_kernel(const float4* __restrict__ X,
                            const float4* __restrict__ W0, const float4* __restrict__ W1,
                            const float4* __restrict__ W2, const float4* __restrict__ W3) {
    const int i = blockIdx.x * blockDim.x + threadIdx.x;
    if (i >= PREP_HALF) return;
    prep_one(i, X, W0, W1, W2, W3);
    const int i2 = i + PREP_HALF;
    if (i2 < PREP_N) prep_one(i2, X, W0, W1, W2, W3);
}

// ---------------------------------------------------------------------------
// Sliding-window attention: AQ=128 tile, 256-key window, streaming online
// softmax over contiguous valid 16-key blocks (R12 version — proven).
// ---------------------------------------------------------------------------
__global__ void __launch_bounds__(256, 2) attn_mma() {
    extern __shared__ char sm[];
    const uint32_t sb = smem_u32(sm);
    const int tid = threadIdx.x;
    const int lane = tid & 31, w = tid >> 5;
    const int bh = blockIdx.y;
    const int q0 = blockIdx.x * AQ;
    const int ks0 = q0 - (WINDOW_ - 1);
    const int jmin = (q0 < WINDOW_ - 1) ? (WINDOW_ - 1 - q0) : 0;

    const __half* Qg = g_QKVh + (size_t)bh * L_ * HD_ + (size_t)q0 * HD_;
    for (int idx = tid; idx < AQ * 8; idx += 256) {
        const int row = idx >> 3, d0 = (idx & 7) * 4;
        const __half* qp = Qg + (size_t)row * HD_ + d0;
        const uint2 ua = *(const uint2*)qp;
        const uint2 ub = *(const uint2*)(qp + 32);
        const __half2* ha = (const __half2*)&ua;
        const __half2* hb = (const __half2*)&ub;
        const float a[4] = {__low2float(ha[0]), __high2float(ha[0]),
                            __low2float(ha[1]), __high2float(ha[1])};
        const float b[4] = {__low2float(hb[0]), __high2float(hb[0]),
                            __low2float(hb[1]), __high2float(hb[1])};
        const float4 cc = *(const float4*)(g_cos + (q0 + row) * 32 + d0);
        const float4 ss = *(const float4*)(g_sin + (q0 + row) * 32 + d0);
        const float c[4] = {cc.x, cc.y, cc.z, cc.w};
        const float s[4] = {ss.x, ss.y, ss.z, ss.w};
        char* p = sm + OFF_Q + row * ASTR + d0 * 2;
#pragma unroll
        for (int e = 0; e < 4; e += 2) {
            *(__half2*)(p + e * 2) = __floats2half2_rn(a[e] * c[e] - b[e] * s[e],
                                                       a[e + 1] * c[e + 1] - b[e + 1] * s[e + 1]);
            *(__half2*)(p + 64 + e * 2) = __floats2half2_rn(b[e] * c[e] + a[e] * s[e],
                                                            b[e + 1] * c[e + 1] + a[e + 1] * s[e + 1]);
        }
    }
    const __half* Kg = g_QKVh + HSZ + (size_t)bh * L_ * HD_;
    for (int idx = tid; idx < ANK * 8; idx += 256) {
        const int row = idx >> 3, d0 = (idx & 7) * 4;
        const int kg = ks0 + row;
        char* p = sm + OFF_K + row * ASTR + d0 * 2;
        if (kg < 0 || kg >= L_) {
            *(uint2*)p = make_uint2(0, 0);
            *(uint2*)(p + 64) = make_uint2(0, 0);
            continue;
        }
        const __half* kp = Kg + (size_t)kg * HD_ + d0;
        const uint2 ua = *(const uint2*)kp;
        const uint2 ub = *(const uint2*)(kp + 32);
        const __half2* ha = (const __half2*)&ua;
        const __half2* hb = (const __half2*)&ub;
        const float a[4] = {__low2float(ha[0]), __high2float(ha[0]),
                            __low2float(ha[1]), __high2float(ha[1])};
        const float b[4] = {__low2float(hb[0]), __high2float(hb[0]),
                            __low2float(hb[1]), __high2float(hb[1])};
        const float4 cc = *(const float4*)(g_cos + kg * 32 + d0);
        const float4 ss = *(const float4*)(g_sin + kg * 32 + d0);
        const float c[4] = {cc.x, cc.y, cc.z, cc.w};
        const float s[4] = {ss.x, ss.y, ss.z, ss.w};
#pragma unroll
        for (int e = 0; e < 4; e += 2) {
            *(__half2*)(p + e * 2) = __floats2half2_rn(a[e] * c[e] - b[e] * s[e],
                                                       a[e + 1] * c[e + 1] - b[e + 1] * s[e + 1]);
            *(__half2*)(p + 64 + e * 2) = __floats2half2_rn(b[e] * c[e] + a[e] * s[e],
                                                            b[e + 1] * c[e + 1] + a[e + 1] * s[e + 1]);
        }
    }
    const __half* Vg = g_QKVh + 2 * HSZ + (size_t)bh * L_ * HD_;
    for (int idx = tid; idx < ANK * 8; idx += 256) {
        const int row = idx >> 3, c8 = idx & 7;
        const int kg = ks0 + row;
        uint4 v = make_uint4(0, 0, 0, 0);
        if (kg >= 0 && kg < L_) v = *(const uint4*)(Vg + (size_t)kg * HD_ + c8 * 8);
        *(uint4*)(sm + OFF_V + row * ASTR + c8 * 16) = v;
    }
    __syncthreads();

    const uint32_t lrow = (lane & 15);
    const uint32_t lh = (lane >> 4) * 16;
    const int rw = 16 * w;

    uint32_t aq[4][4];
#pragma unroll
    for (int kt = 0; kt < 4; kt++)
        LDSM4(aq[kt], sb + OFF_Q + (rw + lrow) * ASTR + kt * 32 + lh);

    const int nb0 = max(0, max(rw, jmin) >> 4);
    const int nb1 = min(15, (rw + 142) >> 4);

    const int i1 = rw + (lane >> 2);
    const int i2 = i1 + 8;
    const int cq = (lane & 3) * 2;
    constexpr float SCALE = 0.125f;

    float m1 = -1e30f, m2 = -1e30f, l1 = 0.f, l2 = 0.f;
    float oac[8][4];
#pragma unroll
    for (int f = 0; f < 8; f++)
#pragma unroll
        for (int k = 0; k < 4; k++) oac[f][k] = 0.f;

    for (int nb = nb0; nb <= nb1; nb++) {
        float sc[2][4];
#pragma unroll
        for (int f = 0; f < 2; f++)
#pragma unroll
            for (int k = 0; k < 4; k++) sc[f][k] = 0.f;
#pragma unroll
        for (int kt = 0; kt < 4; kt++) {
            uint32_t bk[4];
            LDSM4(bk, sb + OFF_K + (nb * 16 + lrow) * ASTR + kt * 32 + lh);
            MMAH(sc[0], aq[kt], bk[0], bk[2]);
            MMAH(sc[1], aq[kt], bk[1], bk[3]);
        }

        bool kk[2][4];
        float bm1 = -1e30f, bm2 = -1e30f;
#pragma unroll
        for (int f = 0; f < 2; f++) {
            const int j0 = nb * 16 + f * 8 + cq, j1 = j0 + 1;
            kk[f][0] = ((unsigned)(j0 - i1) < (unsigned)WINDOW_) && j0 >= jmin;
            kk[f][1] = ((unsigned)(j1 - i1) < (unsigned)WINDOW_) && j1 >= jmin;
            kk[f][2] = ((unsigned)(j0 - i2) < (unsigned)WINDOW_) && j0 >= jmin;
            kk[f][3] = ((unsigned)(j1 - i2) < (unsigned)WINDOW_) && j1 >= jmin;
            sc[f][0] = kk[f][0] ? sc[f][0] * SCALE : -1e30f;
            sc[f][1] = kk[f][1] ? sc[f][1] * SCALE : -1e30f;
            sc[f][2] = kk[f][2] ? sc[f][2] * SCALE : -1e30f;
            sc[f][3] = kk[f][3] ? sc[f][3] * SCALE : -1e30f;
            bm1 = fmaxf(bm1, fmaxf(sc[f][0], sc[f][1]));
            bm2 = fmaxf(bm2, fmaxf(sc[f][2], sc[f][3]));
        }
        bm1 = fmaxf(bm1, __shfl_xor_sync(0xffffffffu, bm1, 1));
        bm1 = fmaxf(bm1, __shfl_xor_sync(0xffffffffu, bm1, 2));
        bm2 = fmaxf(bm2, __shfl_xor_sync(0xffffffffu, bm2, 1));
        bm2 = fmaxf(bm2, __shfl_xor_sync(0xffffffffu, bm2, 2));

        const float M1 = fmaxf(m1, bm1), M2 = fmaxf(m2, bm2);
        const float r1 = __expf(m1 - M1), r2 = __expf(m2 - M2);
        l1 *= r1; l2 *= r2;
#pragma unroll
        for (int f = 0; f < 8; f++) {
            oac[f][0] *= r1; oac[f][1] *= r1;
            oac[f][2] *= r2; oac[f][3] *= r2;
        }

        uint32_t pa[4];
#pragma unroll
        for (int f = 0; f < 2; f++) {
            const float p0 = kk[f][0] ? __expf(sc[f][0] - M1) : 0.f;
            const float p1 = kk[f][1] ? __expf(sc[f][1] - M1) : 0.f;
            const float p2 = kk[f][2] ? __expf(sc[f][2] - M2) : 0.f;
            const float p3 = kk[f][3] ? __expf(sc[f][3] - M2) : 0.f;
            l1 += p0 + p1;
            l2 += p2 + p3;
            pa[2 * f]     = pack_h2(p0, p1);
            pa[2 * f + 1] = pack_h2(p2, p3);
        }

#pragma unroll
        for (int db = 0; db < 4; db++) {
            uint32_t bv[4];
            LDSM4T(bv, sb + OFF_V + (nb * 16 + lrow) * ASTR + db * 32 + lh);
            MMAH(oac[2 * db],     pa, bv[0], bv[1]);
            MMAH(oac[2 * db + 1], pa, bv[2], bv[3]);
        }

        m1 = M1; m2 = M2;
    }

    l1 += __shfl_xor_sync(0xffffffffu, l1, 1);
    l1 += __shfl_xor_sync(0xffffffffu, l1, 2);
    l2 += __shfl_xor_sync(0xffffffffu, l2, 1);
    l2 += __shfl_xor_sync(0xffffffffu, l2, 2);

    const float inv1 = 1.f / l1, inv2 = 1.f / l2;
    const int bb = bh >> 4, h = bh & (H_ - 1);
    const size_t off1 = ((size_t)bb * L_ + q0 + i1) * D_ + h * HD_;
    const size_t off2 = ((size_t)bb * L_ + q0 + i2) * D_ + h * HD_;
#pragma unroll
    for (int f = 0; f < 8; f++) {
        const int d0 = 8 * f + cq;
        *(__half2*)(g_Sh + off1 + d0) =
            __floats2half2_rn(oac[f][0] * inv1, oac[f][1] * inv1);
        *(__half2*)(g_Sh + off2 + d0) =
            __floats2half2_rn(oac[f][2] * inv2, oac[f][3] * inv2);
    }
}

// ---------------------------------------------------------------------------
extern "C" void kernel_launch(void* const* d_in, const int* in_sizes, int n_in,
                              void* d_out, int out_size) {
    const float* X = (const float*)d_in[0];
    float* out = (float*)d_out;

    __half *QKVh, *Sh, *Xh, *Wh;
    cudaGetSymbolAddress((void**)&QKVh, g_QKVh);
    cudaGetSymbolAddress((void**)&Sh, g_Sh);
    cudaGetSymbolAddress((void**)&Xh, g_Xh);
    cudaGetSymbolAddress((void**)&Wh, g_Wh);

    cudaFuncSetAttribute(gemm_mma<0>, cudaFuncAttributeMaxDynamicSharedMemorySize, GSMEM);
    cudaFuncSetAttribute(gemm_mma<1>, cudaFuncAttributeMaxDynamicSharedMemorySize, GSMEM);
    cudaFuncSetAttribute(attn_mma, cudaFuncAttributeMaxDynamicSharedMemorySize, ASMEM);

    prep_kernel<<<(PREP_HALF + 255) / 256, 256>>>((const float4*)X,
                                                  (const float4*)d_in[1], (const float4*)d_in[2],
                                                  (const float4*)d_in[3], (const float4*)d_in[4]);

    gemm_mma<1><<<dim3(D_ / TN, M_ / TM, 3), 256, GSMEM>>>(Xh, Wh, QKVh);

    attn_mma<<<dim3(L_ / AQ, B_ * H_), 256, ASMEM>>>();

    gemm_mma<0><<<dim3(D_ / TN, M_ / TM, 1), 256, GSMEM>>>(Sh, Wh + 3 * (size_t)D_ * D_, out);
}

// round 14
// speedup vs baseline: 1.0016x; 1.0016x over previous
#include <cuda_runtime.h>
#include <cuda_fp16.h>
#include <math.h>
#include <stdint.h>

// Problem constants
constexpr int B_ = 4, L_ = 2048, D_ = 1024, H_ = 16, HD_ = 64;
constexpr int M_ = B_ * L_;
constexpr int WINDOW_ = 128;
constexpr size_t HSZ = (size_t)B_ * H_ * L_ * HD_;

// GEMM tiling (R9/R12 config — proven fastest)
constexpr int TM = 128, TN = 128, KS = 64;
constexpr int NK2 = D_ / KS;
constexpr int ROWB = 144;
constexpr int TILE_B = 128 * ROWB;
constexpr int STAGE_B = 2 * TILE_B;
constexpr int NSTG = 3;
constexpr int GSMEM = NSTG * STAGE_B;       // 110592

// Attention tiling: AQ=128 queries, 256-key window, streaming online softmax
constexpr int AQ = 128;
constexpr int ANK = 256;
constexpr int ASTR = 144;
constexpr int OFF_Q = 0;
constexpr int OFF_K = OFF_Q + AQ * ASTR;    // 18432
constexpr int OFF_V = OFF_K + ANK * ASTR;   // 55296
constexpr int ASMEM = OFF_V + ANK * ASTR;   // 92160

// Scratch (device globals)
__device__ __half g_QKVh[3 * HSZ];
__device__ __half g_Sh[(size_t)M_ * D_];
__device__ __half g_Xh[(size_t)M_ * D_];
__device__ __half g_Wh[4ull * D_ * D_];
__device__ float g_cos[L_ * 32];
__device__ float g_sin[L_ * 32];

__device__ __forceinline__ uint32_t smem_u32(const void* p) {
    uint32_t a;
    asm("{ .reg .u64 t; cvta.to.shared.u64 t, %1; cvt.u32.u64 %0, t; }" : "=r"(a) : "l"(p));
    return a;
}

#define LDSM4(r, addr) \
    asm volatile("ldmatrix.sync.aligned.m8n8.x4.shared.b16 {%0,%1,%2,%3}, [%4];" \
                 : "=r"((r)[0]), "=r"((r)[1]), "=r"((r)[2]), "=r"((r)[3]) : "r"(addr))

#define LDSM4T(r, addr) \
    asm volatile("ldmatrix.sync.aligned.m8n8.x4.trans.shared.b16 {%0,%1,%2,%3}, [%4];" \
                 : "=r"((r)[0]), "=r"((r)[1]), "=r"((r)[2]), "=r"((r)[3]) : "r"(addr))

#define MMAH(d, a, b0, b1) \
    asm volatile("mma.sync.aligned.m16n8k16.row.col.f32.f16.f16.f32 " \
                 "{%0,%1,%2,%3}, {%4,%5,%6,%7}, {%8,%9}, {%0,%1,%2,%3};" \
                 : "+f"((d)[0]), "+f"((d)[1]), "+f"((d)[2]), "+f"((d)[3]) \
                 : "r"((a)[0]), "r"((a)[1]), "r"((a)[2]), "r"((a)[3]), "r"(b0), "r"(b1))

#define CP_WAIT(n) asm volatile("cp.async.wait_group %0;" :: "n"(n) : "memory")

__device__ __forceinline__ void cp16(uint32_t sa, const void* g) {
    asm volatile("cp.async.cg.shared.global [%0], [%1], 16;" :: "r"(sa), "l"(g));
}

__device__ __forceinline__ uint32_t pack_h2(float lo, float hi) {
    __half2 h = __floats2half2_rn(lo, hi);
    return *(uint32_t*)&h;
}

__device__ __forceinline__ void cp_stage(char* st, const __half* a, const __half* wt,
                                         int ko, int tid) {
    const __half* gp[2] = {a, wt};
    const uint32_t sb = smem_u32(st);
#pragma unroll
    for (int t = 0; t < 2; t++) {
#pragma unroll
        for (int rep = 0; rep < 4; rep++) {
            const int c = rep * 256 + tid;
            const int row = c >> 3, ch = c & 7;
            cp16(sb + t * TILE_B + row * ROWB + ch * 16,
                 gp[t] + (size_t)row * D_ + ko + ch * 8);
        }
    }
    asm volatile("cp.async.commit_group;" ::: "memory");
}

// ---------------------------------------------------------------------------
// Single-pass fp16 GEMM with register-level A/B fragment double buffering.
// (Exact R12 configuration — proven fastest: 122 regs, 74.3 us.)
// ---------------------------------------------------------------------------
template <int MODE>
__global__ void __launch_bounds__(256, 2) gemm_mma(const __half* __restrict__ A,
                                                   const __half* __restrict__ Wh,
                                                   void* __restrict__ outv) {
    extern __shared__ char sm[];
    const int tid = threadIdx.x;
    const int lane = tid & 31, wid = tid >> 5;
    const int mw = wid & 1, nw = wid >> 1;
    const int r0 = blockIdx.y * TM, n0 = blockIdx.x * TN;
    const int z = blockIdx.z;

    const __half* A_t = A + (size_t)r0 * D_;
    const __half* W_t = Wh + (size_t)z * D_ * D_ + (size_t)n0 * D_;

    float acc[4][4][4];
#pragma unroll
    for (int i = 0; i < 4; i++)
#pragma unroll
        for (int j = 0; j < 4; j++)
#pragma unroll
            for (int k = 0; k < 4; k++) acc[i][j][k] = 0.f;

    cp_stage(sm + 0 * STAGE_B, A_t, W_t, 0 * KS, tid);
    cp_stage(sm + 1 * STAGE_B, A_t, W_t, 1 * KS, tid);

    const uint32_t lrow = (lane & 15);
    const uint32_t lh = (lane >> 4) * 16;
    const uint32_t arow = (mw * 64 + lrow) * ROWB + lh;
    const uint32_t brow = (nw * 32 + lrow) * ROWB + lh;

    for (int kc = 0; kc < NK2; kc++) {
        const int s = kc % NSTG;
        if (kc + 1 < NK2) { CP_WAIT(1); } else { CP_WAIT(0); }
        __syncthreads();

        const uint32_t sb = smem_u32(sm + s * STAGE_B);
        uint32_t Bb[2][2][4];
        uint32_t Ab[2][4];
        LDSM4(Bb[0][0], sb + TILE_B + brow);
        LDSM4(Bb[0][1], sb + TILE_B + brow + 16 * ROWB);
        LDSM4(Ab[0], sb + arow);

        if (kc + 2 < NK2)
            cp_stage(sm + ((kc + 2) % NSTG) * STAGE_B, A_t, W_t, (kc + 2) * KS, tid);

#pragma unroll
        for (int kt = 0; kt < 4; kt++) {
            const int bc = kt & 1;
            if (kt < 3) {
                LDSM4(Bb[bc ^ 1][0], sb + TILE_B + brow + (kt + 1) * 32);
                LDSM4(Bb[bc ^ 1][1], sb + TILE_B + brow + 16 * ROWB + (kt + 1) * 32);
            }
#pragma unroll
            for (int mt = 0; mt < 4; mt++) {
                const int ac = mt & 1;
                if (mt < 3) {
                    LDSM4(Ab[ac ^ 1], sb + arow + (mt + 1) * 16 * ROWB + kt * 32);
                } else if (kt < 3) {
                    LDSM4(Ab[ac ^ 1], sb + arow + (kt + 1) * 32);
                }
#pragma unroll
                for (int nt = 0; nt < 4; nt++)
                    MMAH(acc[mt][nt], Ab[ac],
                         Bb[bc][nt >> 1][nt & 1], Bb[bc][nt >> 1][(nt & 1) + 2]);
            }
        }
    }

#pragma unroll
    for (int mt = 0; mt < 4; mt++) {
#pragma unroll
        for (int nt = 0; nt < 4; nt++) {
            const int row = r0 + mw * 64 + mt * 16 + (lane >> 2);
            const int col = n0 + nw * 32 + nt * 8 + 2 * (lane & 3);
            if (MODE == 1) {
                __half* out = (__half*)outv + (size_t)z * HSZ;
                const int h = col >> 6, dd = col & 63;
                const int bb0 = row >> 11, l0 = row & (L_ - 1);
                const int r8 = row + 8;
                const int bb1 = r8 >> 11, l1 = r8 & (L_ - 1);
                *(__half2*)(out + (((size_t)bb0 * H_ + h) * L_ + l0) * HD_ + dd) =
                    __floats2half2_rn(acc[mt][nt][0], acc[mt][nt][1]);
                *(__half2*)(out + (((size_t)bb1 * H_ + h) * L_ + l1) * HD_ + dd) =
                    __floats2half2_rn(acc[mt][nt][2], acc[mt][nt][3]);
            } else {
                float* out = (float*)outv;
                *(float2*)(out + (size_t)row * D_ + col) =
                    make_float2(acc[mt][nt][0], acc[mt][nt][1]);
                *(float2*)(out + (size_t)(row + 8) * D_ + col) =
                    make_float2(acc[mt][nt][2], acc[mt][nt][3]);
            }
        }
    }
}

// ---------------------------------------------------------------------------
// Fused prep: X->fp16, W0..W3->fp16, RoPE table. 2 elements per thread.
// ---------------------------------------------------------------------------
constexpr int XN4 = M_ * D_ / 4;
constexpr int WN4 = D_ * D_ / 4;
constexpr int PREP_N = XN4 + 4 * WN4 + L_ * 32;
constexpr int PREP_HALF = (PREP_N + 1) / 2;

__device__ __forceinline__ void prep_one(int i, const float4* __restrict__ X,
                                         const float4* __restrict__ W0,
                                         const float4* __restrict__ W1,
                                         const float4* __restrict__ W2,
                                         const float4* __restrict__ W3) {
    if (i < XN4) {
        const float4 v = X[i];
        __half2* o = (__half2*)g_Xh;
        o[2 * i]     = __floats2half2_rn(v.x, v.y);
        o[2 * i + 1] = __floats2half2_rn(v.z, v.w);
    } else if (i < XN4 + 4 * WN4) {
        const int widx = i - XN4;
        const int wi = widx >> 18, off = widx & (WN4 - 1);
        const float4* Wp = (wi == 0) ? W0 : (wi == 1) ? W1 : (wi == 2) ? W2 : W3;
        const float4 v = Wp[off];
        __half2* o = (__half2*)(g_Wh + (size_t)wi * D_ * D_);
        o[2 * off]     = __floats2half2_rn(v.x, v.y);
        o[2 * off + 1] = __floats2half2_rn(v.z, v.w);
    } else {
        const int r = i - XN4 - 4 * WN4;
        if (r < L_ * 32) {
            const int j = r & 31, l = r >> 5;
            const float invf = expf(-(float)j * 0.28782313662425575f);
            float s, c;
            sincosf((float)l * invf, &s, &c);
            g_cos[r] = c;
            g_sin[r] = s;
        }
    }
}

__global__ void prep_kernel(const float4* __restrict__ X,
                            const float4* __restrict__ W0, const float4* __restrict__ W1,
                            const float4* __restrict__ W2, const float4* __restrict__ W3) {
    const int i = blockIdx.x * blockDim.x + threadIdx.x;
    if (i >= PREP_HALF) return;
    prep_one(i, X, W0, W1, W2, W3);
    const int i2 = i + PREP_HALF;
    if (i2 < PREP_N) prep_one(i2, X, W0, W1, W2, W3);
}

// ---------------------------------------------------------------------------
// Sliding-window attention: AQ=128 tile, 256-key window, streaming online
// softmax over contiguous valid 16-key blocks (R12 version — proven).
// ---------------------------------------------------------------------------
__global__ void __launch_bounds__(256, 2) attn_mma() {
    extern __shared__ char sm[];
    const uint32_t sb = smem_u32(sm);
    const int tid = threadIdx.x;
    const int lane = tid & 31, w = tid >> 5;
    const int bh = blockIdx.y;
    const int q0 = blockIdx.x * AQ;
    const int ks0 = q0 - (WINDOW_ - 1);
    const int jmin = (q0 < WINDOW_ - 1) ? (WINDOW_ - 1 - q0) : 0;

    const __half* Qg = g_QKVh + (size_t)bh * L_ * HD_ + (size_t)q0 * HD_;
    for (int idx = tid; idx < AQ * 8; idx += 256) {
        const int row = idx >> 3, d0 = (idx & 7) * 4;
        const __half* qp = Qg + (size_t)row * HD_ + d0;
        const uint2 ua = *(const uint2*)qp;
        const uint2 ub = *(const uint2*)(qp + 32);
        const __half2* ha = (const __half2*)&ua;
        const __half2* hb = (const __half2*)&ub;
        const float a[4] = {__low2float(ha[0]), __high2float(ha[0]),
                            __low2float(ha[1]), __high2float(ha[1])};
        const float b[4] = {__low2float(hb[0]), __high2float(hb[0]),
                            __low2float(hb[1]), __high2float(hb[1])};
        const float4 cc = *(const float4*)(g_cos + (q0 + row) * 32 + d0);
        const float4 ss = *(const float4*)(g_sin + (q0 + row) * 32 + d0);
        const float c[4] = {cc.x, cc.y, cc.z, cc.w};
        const float s[4] = {ss.x, ss.y, ss.z, ss.w};
        char* p = sm + OFF_Q + row * ASTR + d0 * 2;
#pragma unroll
        for (int e = 0; e < 4; e += 2) {
            *(__half2*)(p + e * 2) = __floats2half2_rn(a[e] * c[e] - b[e] * s[e],
                                                       a[e + 1] * c[e + 1] - b[e + 1] * s[e + 1]);
            *(__half2*)(p + 64 + e * 2) = __floats2half2_rn(b[e] * c[e] + a[e] * s[e],
                                                            b[e + 1] * c[e + 1] + a[e + 1] * s[e + 1]);
        }
    }
    const __half* Kg = g_QKVh + HSZ + (size_t)bh * L_ * HD_;
    for (int idx = tid; idx < ANK * 8; idx += 256) {
        const int row = idx >> 3, d0 = (idx & 7) * 4;
        const int kg = ks0 + row;
        char* p = sm + OFF_K + row * ASTR + d0 * 2;
        if (kg < 0 || kg >= L_) {
            *(uint2*)p = make_uint2(0, 0);
            *(uint2*)(p + 64) = make_uint2(0, 0);
            continue;
        }
        const __half* kp = Kg + (size_t)kg * HD_ + d0;
        const uint2 ua = *(const uint2*)kp;
        const uint2 ub = *(const uint2*)(kp + 32);
        const __half2* ha = (const __half2*)&ua;
        const __half2* hb = (const __half2*)&ub;
        const float a[4] = {__low2float(ha[0]), __high2float(ha[0]),
                            __low2float(ha[1]), __high2float(ha[1])};
        const float b[4] = {__low2float(hb[0]), __high2float(hb[0]),
                            __low2float(hb[1]), __high2float(hb[1])};
        const float4 cc = *(const float4*)(g_cos + kg * 32 + d0);
        const float4 ss = *(const float4*)(g_sin + kg * 32 + d0);
        const float c[4] = {cc.x, cc.y, cc.z, cc.w};
        const float s[4] = {ss.x, ss.y, ss.z, ss.w};
#pragma unroll
        for (int e = 0; e < 4; e += 2) {
            *(__half2*)(p + e * 2) = __floats2half2_rn(a[e] * c[e] - b[e] * s[e],
                                                       a[e + 1] * c[e + 1] - b[e + 1] * s[e + 1]);
            *(__half2*)(p + 64 + e * 2) = __floats2half2_rn(b[e] * c[e] + a[e] * s[e],
                                                            b[e + 1] * c[e + 1] + a[e + 1] * s[e + 1]);
        }
    }
    const __half* Vg = g_QKVh + 2 * HSZ + (size_t)bh * L_ * HD_;
    for (int idx = tid; idx < ANK * 8; idx += 256) {
        const int row = idx >> 3, c8 = idx & 7;
        const int kg = ks0 + row;
        uint4 v = make_uint4(0, 0, 0, 0);
        if (kg >= 0 && kg < L_) v = *(const uint4*)(Vg + (size_t)kg * HD_ + c8 * 8);
        *(uint4*)(sm + OFF_V + row * ASTR + c8 * 16) = v;
    }
    __syncthreads();

    const uint32_t lrow = (lane & 15);
    const uint32_t lh = (lane >> 4) * 16;
    const int rw = 16 * w;

    uint32_t aq[4][4];
#pragma unroll
    for (int kt = 0; kt < 4; kt++)
        LDSM4(aq[kt], sb + OFF_Q + (rw + lrow) * ASTR + kt * 32 + lh);

    const int nb0 = max(0, max(rw, jmin) >> 4);
    const int nb1 = min(15, (rw + 142) >> 4);

    const int i1 = rw + (lane >> 2);
    const int i2 = i1 + 8;
    const int cq = (lane & 3) * 2;
    constexpr float SCALE = 0.125f;

    float m1 = -1e30f, m2 = -1e30f, l1 = 0.f, l2 = 0.f;
    float oac[8][4];
#pragma unroll
    for (int f = 0; f < 8; f++)
#pragma unroll
        for (int k = 0; k < 4; k++) oac[f][k] = 0.f;

    for (int nb = nb0; nb <= nb1; nb++) {
        float sc[2][4];
#pragma unroll
        for (int f = 0; f < 2; f++)
#pragma unroll
            for (int k = 0; k < 4; k++) sc[f][k] = 0.f;
#pragma unroll
        for (int kt = 0; kt < 4; kt++) {
            uint32_t bk[4];
            LDSM4(bk, sb + OFF_K + (nb * 16 + lrow) * ASTR + kt * 32 + lh);
            MMAH(sc[0], aq[kt], bk[0], bk[2]);
            MMAH(sc[1], aq[kt], bk[1], bk[3]);
        }

        bool kk[2][4];
        float bm1 = -1e30f, bm2 = -1e30f;
#pragma unroll
        for (int f = 0; f < 2; f++) {
            const int j0 = nb * 16 + f * 8 + cq, j1 = j0 + 1;
            kk[f][0] = ((unsigned)(j0 - i1) < (unsigned)WINDOW_) && j0 >= jmin;
            kk[f][1] = ((unsigned)(j1 - i1) < (unsigned)WINDOW_) && j1 >= jmin;
            kk[f][2] = ((unsigned)(j0 - i2) < (unsigned)WINDOW_) && j0 >= jmin;
            kk[f][3] = ((unsigned)(j1 - i2) < (unsigned)WINDOW_) && j1 >= jmin;
            sc[f][0] = kk[f][0] ? sc[f][0] * SCALE : -1e30f;
            sc[f][1] = kk[f][1] ? sc[f][1] * SCALE : -1e30f;
            sc[f][2] = kk[f][2] ? sc[f][2] * SCALE : -1e30f;
            sc[f][3] = kk[f][3] ? sc[f][3] * SCALE : -1e30f;
            bm1 = fmaxf(bm1, fmaxf(sc[f][0], sc[f][1]));
            bm2 = fmaxf(bm2, fmaxf(sc[f][2], sc[f][3]));
        }
        bm1 = fmaxf(bm1, __shfl_xor_sync(0xffffffffu, bm1, 1));
        bm1 = fmaxf(bm1, __shfl_xor_sync(0xffffffffu, bm1, 2));
        bm2 = fmaxf(bm2, __shfl_xor_sync(0xffffffffu, bm2, 1));
        bm2 = fmaxf(bm2, __shfl_xor_sync(0xffffffffu, bm2, 2));

        const float M1 = fmaxf(m1, bm1), M2 = fmaxf(m2, bm2);
        const float r1 = __expf(m1 - M1), r2 = __expf(m2 - M2);
        l1 *= r1; l2 *= r2;
#pragma unroll
        for (int f = 0; f < 8; f++) {
            oac[f][0] *= r1; oac[f][1] *= r1;
            oac[f][2] *= r2; oac[f][3] *= r2;
        }

        uint32_t pa[4];
#pragma unroll
        for (int f = 0; f < 2; f++) {
            const float p0 = kk[f][0] ? __expf(sc[f][0] - M1) : 0.f;
            const float p1 = kk[f][1] ? __expf(sc[f][1] - M1) : 0.f;
            const float p2 = kk[f][2] ? __expf(sc[f][2] - M2) : 0.f;
            const float p3 = kk[f][3] ? __expf(sc[f][3] - M2) : 0.f;
            l1 += p0 + p1;
            l2 += p2 + p3;
            pa[2 * f]     = pack_h2(p0, p1);
            pa[2 * f + 1] = pack_h2(p2, p3);
        }

#pragma unroll
        for (int db = 0; db < 4; db++) {
            uint32_t bv[4];
            LDSM4T(bv, sb + OFF_V + (nb * 16 + lrow) * ASTR + db * 32 + lh);
            MMAH(oac[2 * db],     pa, bv[0], bv[1]);
            MMAH(oac[2 * db + 1], pa, bv[2], bv[3]);
        }

        m1 = M1; m2 = M2;
    }

    l1 += __shfl_xor_sync(0xffffffffu, l1, 1);
    l1 += __shfl_xor_sync(0xffffffffu, l1, 2);
    l2 += __shfl_xor_sync(0xffffffffu, l2, 1);
    l2 += __shfl_xor_sync(0xffffffffu, l2, 2);

    const float inv1 = 1.f / l1, inv2 = 1.f / l2;
    const int bb = bh >> 4, h = bh & (H_ - 1);
    const size_t off1 = ((size_t)bb * L_ + q0 + i1) * D_ + h * HD_;
    const size_t off2 = ((size_t)bb * L_ + q0 + i2) * D_ + h * HD_;
#pragma unroll
    for (int f = 0; f < 8; f++) {
        const int d0 = 8 * f + cq;
        *(__half2*)(g_Sh + off1 + d0) =
            __floats2half2_rn(oac[f][0] * inv1, oac[f][1] * inv1);
        *(__half2*)(g_Sh + off2 + d0) =
            __floats2half2_rn(oac[f][2] * inv2, oac[f][3] * inv2);
    }
}

// ---------------------------------------------------------------------------
extern "C" void kernel_launch(void* const* d_in, const int* in_sizes, int n_in,
                              void* d_out, int out_size) {
    const float* X = (const float*)d_in[0];
    float* out = (float*)d_out;

    __half *QKVh, *Sh, *Xh, *Wh;
    cudaGetSymbolAddress((void**)&QKVh, g_QKVh);
    cudaGetSymbolAddress((void**)&Sh, g_Sh);
    cudaGetSymbolAddress((void**)&Xh, g_Xh);
    cudaGetSymbolAddress((void**)&Wh, g_Wh);

    cudaFuncSetAttribute(gemm_mma<0>, cudaFuncAttributeMaxDynamicSharedMemorySize, GSMEM);
    cudaFuncSetAttribute(gemm_mma<1>, cudaFuncAttributeMaxDynamicSharedMemorySize, GSMEM);
    cudaFuncSetAttribute(attn_mma, cudaFuncAttributeMaxDynamicSharedMemorySize, ASMEM);

    prep_kernel<<<(PREP_HALF + 255) / 256, 256>>>((const float4*)X,
                                                  (const float4*)d_in[1], (const float4*)d_in[2],
                                                  (const float4*)d_in[3], (const float4*)d_in[4]);

    gemm_mma<1><<<dim3(D_ / TN, M_ / TM, 3), 256, GSMEM>>>(Xh, Wh, QKVh);

    attn_mma<<<dim3(L_ / AQ, B_ * H_), 256, ASMEM>>>();

    gemm_mma<0><<<dim3(D_ / TN, M_ / TM, 1), 256, GSMEM>>>(Sh, Wh + 3 * (size_t)D_ * D_, out);
}

// round 15
// speedup vs baseline: 1.0322x; 1.0306x over previous
#include <cuda_runtime.h>
#include <cuda_fp16.h>
#include <math.h>
#include <stdint.h>

// Problem constants
constexpr int B_ = 4, L_ = 2048, D_ = 1024, H_ = 16, HD_ = 64;
constexpr int M_ = B_ * L_;
constexpr int WINDOW_ = 128;
constexpr size_t HSZ = (size_t)B_ * H_ * L_ * HD_;

// GEMM tiling (R12 config — proven fastest)
constexpr int TM = 128, TN = 128, KS = 64;
constexpr int NK2 = D_ / KS;
constexpr int ROWB = 144;
constexpr int TILE_B = 128 * ROWB;
constexpr int STAGE_B = 2 * TILE_B;
constexpr int NSTG = 3;
constexpr int GSMEM = NSTG * STAGE_B;       // 110592

// Attention tiling: AQ=128 queries, 256-key window, streaming online softmax
constexpr int AQ = 128;
constexpr int ANK = 256;
constexpr int ASTR = 144;
constexpr int OFF_Q = 0;
constexpr int OFF_K = OFF_Q + AQ * ASTR;    // 18432
constexpr int OFF_V = OFF_K + ANK * ASTR;   // 55296
// (attention smem 92160 <= GSMEM; fused kernel uses GSMEM)

// Fused grid: 1536 GEMM CTAs (8 x 64 x 3) then 1024 attention CTAs (16 x 64)
constexpr int N_GEMM_CTAS = 1536;
constexpr int N_ATTN_CTAS = (L_ / AQ) * (B_ * H_);   // 1024

// Scratch (device globals)
__device__ __half g_QKVh[3 * HSZ];
__device__ __half g_Sh[(size_t)M_ * D_];
__device__ __half g_Xh[(size_t)M_ * D_];
__device__ __half g_Wh[4ull * D_ * D_];
__device__ float g_cos[L_ * 32];
__device__ float g_sin[L_ * 32];
__device__ int g_cnt[3 * 64];               // per (z, row-block) completion counters

__device__ __forceinline__ uint32_t smem_u32(const void* p) {
    uint32_t a;
    asm("{ .reg .u64 t; cvta.to.shared.u64 t, %1; cvt.u32.u64 %0, t; }" : "=r"(a) : "l"(p));
    return a;
}

#define LDSM4(r, addr) \
    asm volatile("ldmatrix.sync.aligned.m8n8.x4.shared.b16 {%0,%1,%2,%3}, [%4];" \
                 : "=r"((r)[0]), "=r"((r)[1]), "=r"((r)[2]), "=r"((r)[3]) : "r"(addr))

#define LDSM4T(r, addr) \
    asm volatile("ldmatrix.sync.aligned.m8n8.x4.trans.shared.b16 {%0,%1,%2,%3}, [%4];" \
                 : "=r"((r)[0]), "=r"((r)[1]), "=r"((r)[2]), "=r"((r)[3]) : "r"(addr))

#define MMAH(d, a, b0, b1) \
    asm volatile("mma.sync.aligned.m16n8k16.row.col.f32.f16.f16.f32 " \
                 "{%0,%1,%2,%3}, {%4,%5,%6,%7}, {%8,%9}, {%0,%1,%2,%3};" \
                 : "+f"((d)[0]), "+f"((d)[1]), "+f"((d)[2]), "+f"((d)[3]) \
                 : "r"((a)[0]), "r"((a)[1]), "r"((a)[2]), "r"((a)[3]), "r"(b0), "r"(b1))

#define CP_WAIT(n) asm volatile("cp.async.wait_group %0;" :: "n"(n) : "memory")

__device__ __forceinline__ void cp16(uint32_t sa, const void* g) {
    asm volatile("cp.async.cg.shared.global [%0], [%1], 16;" :: "r"(sa), "l"(g));
}

__device__ __forceinline__ uint32_t pack_h2(float lo, float hi) {
    __half2 h = __floats2half2_rn(lo, hi);
    return *(uint32_t*)&h;
}

__device__ __forceinline__ void cp_stage(char* st, const __half* a, const __half* wt,
                                         int ko, int tid) {
    const __half* gp[2] = {a, wt};
    const uint32_t sb = smem_u32(st);
#pragma unroll
    for (int t = 0; t < 2; t++) {
#pragma unroll
        for (int rep = 0; rep < 4; rep++) {
            const int c = rep * 256 + tid;
            const int row = c >> 3, ch = c & 7;
            cp16(sb + t * TILE_B + row * ROWB + ch * 16,
                 gp[t] + (size_t)row * D_ + ko + ch * 8);
        }
    }
    asm volatile("cp.async.commit_group;" ::: "memory");
}

// ---------------------------------------------------------------------------
// GEMM mainloop body (R12 config). MODE 0: fp32 row-major. MODE 1: fp16
// head-scatter. Callable from standalone or fused kernel.
// ---------------------------------------------------------------------------
template <int MODE>
__device__ __forceinline__ void gemm_body(char* sm, int xb, int yb, int z,
                                          const __half* __restrict__ A,
                                          const __half* __restrict__ Wh,
                                          void* __restrict__ outv) {
    const int tid = threadIdx.x;
    const int lane = tid & 31, wid = tid >> 5;
    const int mw = wid & 1, nw = wid >> 1;
    const int r0 = yb * TM, n0 = xb * TN;

    const __half* A_t = A + (size_t)r0 * D_;
    const __half* W_t = Wh + (size_t)z * D_ * D_ + (size_t)n0 * D_;

    float acc[4][4][4];
#pragma unroll
    for (int i = 0; i < 4; i++)
#pragma unroll
        for (int j = 0; j < 4; j++)
#pragma unroll
            for (int k = 0; k < 4; k++) acc[i][j][k] = 0.f;

    cp_stage(sm + 0 * STAGE_B, A_t, W_t, 0 * KS, tid);
    cp_stage(sm + 1 * STAGE_B, A_t, W_t, 1 * KS, tid);

    const uint32_t lrow = (lane & 15);
    const uint32_t lh = (lane >> 4) * 16;
    const uint32_t arow = (mw * 64 + lrow) * ROWB + lh;
    const uint32_t brow = (nw * 32 + lrow) * ROWB + lh;

    for (int kc = 0; kc < NK2; kc++) {
        const int s = kc % NSTG;
        if (kc + 1 < NK2) { CP_WAIT(1); } else { CP_WAIT(0); }
        __syncthreads();

        const uint32_t sb = smem_u32(sm + s * STAGE_B);
        uint32_t Bb[2][2][4];
        uint32_t Ab[2][4];
        LDSM4(Bb[0][0], sb + TILE_B + brow);
        LDSM4(Bb[0][1], sb + TILE_B + brow + 16 * ROWB);
        LDSM4(Ab[0], sb + arow);

        if (kc + 2 < NK2)
            cp_stage(sm + ((kc + 2) % NSTG) * STAGE_B, A_t, W_t, (kc + 2) * KS, tid);

#pragma unroll
        for (int kt = 0; kt < 4; kt++) {
            const int bc = kt & 1;
            if (kt < 3) {
                LDSM4(Bb[bc ^ 1][0], sb + TILE_B + brow + (kt + 1) * 32);
                LDSM4(Bb[bc ^ 1][1], sb + TILE_B + brow + 16 * ROWB + (kt + 1) * 32);
            }
#pragma unroll
            for (int mt = 0; mt < 4; mt++) {
                const int ac = mt & 1;
                if (mt < 3) {
                    LDSM4(Ab[ac ^ 1], sb + arow + (mt + 1) * 16 * ROWB + kt * 32);
                } else if (kt < 3) {
                    LDSM4(Ab[ac ^ 1], sb + arow + (kt + 1) * 32);
                }
#pragma unroll
                for (int nt = 0; nt < 4; nt++)
                    MMAH(acc[mt][nt], Ab[ac],
                         Bb[bc][nt >> 1][nt & 1], Bb[bc][nt >> 1][(nt & 1) + 2]);
            }
        }
    }

#pragma unroll
    for (int mt = 0; mt < 4; mt++) {
#pragma unroll
        for (int nt = 0; nt < 4; nt++) {
            const int row = r0 + mw * 64 + mt * 16 + (lane >> 2);
            const int col = n0 + nw * 32 + nt * 8 + 2 * (lane & 3);
            if (MODE == 1) {
                __half* out = (__half*)outv + (size_t)z * HSZ;
                const int h = col >> 6, dd = col & 63;
                const int bb0 = row >> 11, l0 = row & (L_ - 1);
                const int r8 = row + 8;
                const int bb1 = r8 >> 11, l1 = r8 & (L_ - 1);
                *(__half2*)(out + (((size_t)bb0 * H_ + h) * L_ + l0) * HD_ + dd) =
                    __floats2half2_rn(acc[mt][nt][0], acc[mt][nt][1]);
                *(__half2*)(out + (((size_t)bb1 * H_ + h) * L_ + l1) * HD_ + dd) =
                    __floats2half2_rn(acc[mt][nt][2], acc[mt][nt][3]);
            } else {
                float* out = (float*)outv;
                *(float2*)(out + (size_t)row * D_ + col) =
                    make_float2(acc[mt][nt][0], acc[mt][nt][1]);
                *(float2*)(out + (size_t)(row + 8) * D_ + col) =
                    make_float2(acc[mt][nt][2], acc[mt][nt][3]);
            }
        }
    }
}

// ---------------------------------------------------------------------------
// Attention body (R12 streaming config). Assumes dependency wait already done.
// ---------------------------------------------------------------------------
__device__ __forceinline__ void attn_body(char* sm, int qt, int bh) {
    const uint32_t sb = smem_u32(sm);
    const int tid = threadIdx.x;
    const int lane = tid & 31, w = tid >> 5;
    const int q0 = qt * AQ;
    const int ks0 = q0 - (WINDOW_ - 1);
    const int jmin = (q0 < WINDOW_ - 1) ? (WINDOW_ - 1 - q0) : 0;

    const __half* Qg = g_QKVh + (size_t)bh * L_ * HD_ + (size_t)q0 * HD_;
    for (int idx = tid; idx < AQ * 8; idx += 256) {
        const int row = idx >> 3, d0 = (idx & 7) * 4;
        const __half* qp = Qg + (size_t)row * HD_ + d0;
        const uint2 ua = *(const uint2*)qp;
        const uint2 ub = *(const uint2*)(qp + 32);
        const __half2* ha = (const __half2*)&ua;
        const __half2* hb = (const __half2*)&ub;
        const float a[4] = {__low2float(ha[0]), __high2float(ha[0]),
                            __low2float(ha[1]), __high2float(ha[1])};
        const float b[4] = {__low2float(hb[0]), __high2float(hb[0]),
                            __low2float(hb[1]), __high2float(hb[1])};
        const float4 cc = *(const float4*)(g_cos + (q0 + row) * 32 + d0);
        const float4 ss = *(const float4*)(g_sin + (q0 + row) * 32 + d0);
        const float c[4] = {cc.x, cc.y, cc.z, cc.w};
        const float s[4] = {ss.x, ss.y, ss.z, ss.w};
        char* p = sm + OFF_Q + row * ASTR + d0 * 2;
#pragma unroll
        for (int e = 0; e < 4; e += 2) {
            *(__half2*)(p + e * 2) = __floats2half2_rn(a[e] * c[e] - b[e] * s[e],
                                                       a[e + 1] * c[e + 1] - b[e + 1] * s[e + 1]);
            *(__half2*)(p + 64 + e * 2) = __floats2half2_rn(b[e] * c[e] + a[e] * s[e],
                                                            b[e + 1] * c[e + 1] + a[e + 1] * s[e + 1]);
        }
    }
    const __half* Kg = g_QKVh + HSZ + (size_t)bh * L_ * HD_;
    for (int idx = tid; idx < ANK * 8; idx += 256) {
        const int row = idx >> 3, d0 = (idx & 7) * 4;
        const int kg = ks0 + row;
        char* p = sm + OFF_K + row * ASTR + d0 * 2;
        if (kg < 0 || kg >= L_) {
            *(uint2*)p = make_uint2(0, 0);
            *(uint2*)(p + 64) = make_uint2(0, 0);
            continue;
        }
        const __half* kp = Kg + (size_t)kg * HD_ + d0;
        const uint2 ua = *(const uint2*)kp;
        const uint2 ub = *(const uint2*)(kp + 32);
        const __half2* ha = (const __half2*)&ua;
        const __half2* hb = (const __half2*)&ub;
        const float a[4] = {__low2float(ha[0]), __high2float(ha[0]),
                            __low2float(ha[1]), __high2float(ha[1])};
        const float b[4] = {__low2float(hb[0]), __high2float(hb[0]),
                            __low2float(hb[1]), __high2float(hb[1])};
        const float4 cc = *(const float4*)(g_cos + kg * 32 + d0);
        const float4 ss = *(const float4*)(g_sin + kg * 32 + d0);
        const float c[4] = {cc.x, cc.y, cc.z, cc.w};
        const float s[4] = {ss.x, ss.y, ss.z, ss.w};
#pragma unroll
        for (int e = 0; e < 4; e += 2) {
            *(__half2*)(p + e * 2) = __floats2half2_rn(a[e] * c[e] - b[e] * s[e],
                                                       a[e + 1] * c[e + 1] - b[e + 1] * s[e + 1]);
            *(__half2*)(p + 64 + e * 2) = __floats2half2_rn(b[e] * c[e] + a[e] * s[e],
                                                            b[e + 1] * c[e + 1] + a[e + 1] * s[e + 1]);
        }
    }
    const __half* Vg = g_QKVh + 2 * HSZ + (size_t)bh * L_ * HD_;
    for (int idx = tid; idx < ANK * 8; idx += 256) {
        const int row = idx >> 3, c8 = idx & 7;
        const int kg = ks0 + row;
        uint4 v = make_uint4(0, 0, 0, 0);
        if (kg >= 0 && kg < L_) v = *(const uint4*)(Vg + (size_t)kg * HD_ + c8 * 8);
        *(uint4*)(sm + OFF_V + row * ASTR + c8 * 16) = v;
    }
    __syncthreads();

    const uint32_t lrow = (lane & 15);
    const uint32_t lh = (lane >> 4) * 16;
    const int rw = 16 * w;

    uint32_t aq[4][4];
#pragma unroll
    for (int kt = 0; kt < 4; kt++)
        LDSM4(aq[kt], sb + OFF_Q + (rw + lrow) * ASTR + kt * 32 + lh);

    const int nb0 = max(0, max(rw, jmin) >> 4);
    const int nb1 = min(15, (rw + 142) >> 4);

    const int i1 = rw + (lane >> 2);
    const int i2 = i1 + 8;
    const int cq = (lane & 3) * 2;
    constexpr float SCALE = 0.125f;

    float m1 = -1e30f, m2 = -1e30f, l1 = 0.f, l2 = 0.f;
    float oac[8][4];
#pragma unroll
    for (int f = 0; f < 8; f++)
#pragma unroll
        for (int k = 0; k < 4; k++) oac[f][k] = 0.f;

    for (int nb = nb0; nb <= nb1; nb++) {
        float sc[2][4];
#pragma unroll
        for (int f = 0; f < 2; f++)
#pragma unroll
            for (int k = 0; k < 4; k++) sc[f][k] = 0.f;
#pragma unroll
        for (int kt = 0; kt < 4; kt++) {
            uint32_t bk[4];
            LDSM4(bk, sb + OFF_K + (nb * 16 + lrow) * ASTR + kt * 32 + lh);
            MMAH(sc[0], aq[kt], bk[0], bk[2]);
            MMAH(sc[1], aq[kt], bk[1], bk[3]);
        }

        bool kk[2][4];
        float bm1 = -1e30f, bm2 = -1e30f;
#pragma unroll
        for (int f = 0; f < 2; f++) {
            const int j0 = nb * 16 + f * 8 + cq, j1 = j0 + 1;
            kk[f][0] = ((unsigned)(j0 - i1) < (unsigned)WINDOW_) && j0 >= jmin;
            kk[f][1] = ((unsigned)(j1 - i1) < (unsigned)WINDOW_) && j1 >= jmin;
            kk[f][2] = ((unsigned)(j0 - i2) < (unsigned)WINDOW_) && j0 >= jmin;
            kk[f][3] = ((unsigned)(j1 - i2) < (unsigned)WINDOW_) && j1 >= jmin;
            sc[f][0] = kk[f][0] ? sc[f][0] * SCALE : -1e30f;
            sc[f][1] = kk[f][1] ? sc[f][1] * SCALE : -1e30f;
            sc[f][2] = kk[f][2] ? sc[f][2] * SCALE : -1e30f;
            sc[f][3] = kk[f][3] ? sc[f][3] * SCALE : -1e30f;
            bm1 = fmaxf(bm1, fmaxf(sc[f][0], sc[f][1]));
            bm2 = fmaxf(bm2, fmaxf(sc[f][2], sc[f][3]));
        }
        bm1 = fmaxf(bm1, __shfl_xor_sync(0xffffffffu, bm1, 1));
        bm1 = fmaxf(bm1, __shfl_xor_sync(0xffffffffu, bm1, 2));
        bm2 = fmaxf(bm2, __shfl_xor_sync(0xffffffffu, bm2, 1));
        bm2 = fmaxf(bm2, __shfl_xor_sync(0xffffffffu, bm2, 2));

        const float M1 = fmaxf(m1, bm1), M2 = fmaxf(m2, bm2);
        const float r1 = __expf(m1 - M1), r2 = __expf(m2 - M2);
        l1 *= r1; l2 *= r2;
#pragma unroll
        for (int f = 0; f < 8; f++) {
            oac[f][0] *= r1; oac[f][1] *= r1;
            oac[f][2] *= r2; oac[f][3] *= r2;
        }

        uint32_t pa[4];
#pragma unroll
        for (int f = 0; f < 2; f++) {
            const float p0 = kk[f][0] ? __expf(sc[f][0] - M1) : 0.f;
            const float p1 = kk[f][1] ? __expf(sc[f][1] - M1) : 0.f;
            const float p2 = kk[f][2] ? __expf(sc[f][2] - M2) : 0.f;
            const float p3 = kk[f][3] ? __expf(sc[f][3] - M2) : 0.f;
            l1 += p0 + p1;
            l2 += p2 + p3;
            pa[2 * f]     = pack_h2(p0, p1);
            pa[2 * f + 1] = pack_h2(p2, p3);
        }

#pragma unroll
        for (int db = 0; db < 4; db++) {
            uint32_t bv[4];
            LDSM4T(bv, sb + OFF_V + (nb * 16 + lrow) * ASTR + db * 32 + lh);
            MMAH(oac[2 * db],     pa, bv[0], bv[1]);
            MMAH(oac[2 * db + 1], pa, bv[2], bv[3]);
        }

        m1 = M1; m2 = M2;
    }

    l1 += __shfl_xor_sync(0xffffffffu, l1, 1);
    l1 += __shfl_xor_sync(0xffffffffu, l1, 2);
    l2 += __shfl_xor_sync(0xffffffffu, l2, 1);
    l2 += __shfl_xor_sync(0xffffffffu, l2, 2);

    const float inv1 = 1.f / l1, inv2 = 1.f / l2;
    const int bb = bh >> 4, h = bh & (H_ - 1);
    const size_t off1 = ((size_t)bb * L_ + q0 + i1) * D_ + h * HD_;
    const size_t off2 = ((size_t)bb * L_ + q0 + i2) * D_ + h * HD_;
#pragma unroll
    for (int f = 0; f < 8; f++) {
        const int d0 = 8 * f + cq;
        *(__half2*)(g_Sh + off1 + d0) =
            __floats2half2_rn(oac[f][0] * inv1, oac[f][1] * inv1);
        *(__half2*)(g_Sh + off2 + d0) =
            __floats2half2_rn(oac[f][2] * inv2, oac[f][3] * inv2);
    }
}

// ---------------------------------------------------------------------------
// Fused QKV-GEMM + attention. GEMM CTAs signal per-(z,row-block) counters;
// attention CTAs spin on their 6 dependencies, then run. Attention rides the
// GEMM tail's idle slots.
// ---------------------------------------------------------------------------
__global__ void __launch_bounds__(256, 2) qkv_attn_fused(const __half* __restrict__ Xh,
                                                         const __half* __restrict__ Wh) {
    extern __shared__ char sm[];
    const int b = blockIdx.x;
    if (b < N_GEMM_CTAS) {
        const int xb = b & 7, yb = (b >> 3) & 63, z = b >> 9;
        gemm_body<1>(sm, xb, yb, z, Xh, Wh, (void*)g_QKVh);
        __threadfence();
        __syncthreads();
        if (threadIdx.x == 0)
            atomicAdd(&g_cnt[z * 64 + yb], 1);
    } else {
        const int ab = b - N_GEMM_CTAS;
        const int qt = ab & 15, bh = ab >> 4;
        const int bb = bh >> 4;
        const int y1 = bb * 16 + qt;                 // row-block of this q-tile
        const int y0 = (qt > 0) ? (y1 - 1) : y1;     // previous block (window keys)
        if (threadIdx.x == 0) {
            volatile int* vc = g_cnt;
            for (;;) {
                const bool ok = vc[0 * 64 + y0] == 8 && vc[0 * 64 + y1] == 8 &&
                                vc[1 * 64 + y0] == 8 && vc[1 * 64 + y1] == 8 &&
                                vc[2 * 64 + y0] == 8 && vc[2 * 64 + y1] == 8;
                if (ok) break;
                __nanosleep(128);
            }
        }
        __syncthreads();
        attn_body(sm, qt, bh);
    }
}

// ---------------------------------------------------------------------------
// Standalone GEMM kernel (O-projection, MODE 0)
// ---------------------------------------------------------------------------
__global__ void __launch_bounds__(256, 2) gemm_o(const __half* __restrict__ A,
                                                 const __half* __restrict__ Wh,
                                                 float* __restrict__ out) {
    extern __shared__ char sm[];
    gemm_body<0>(sm, blockIdx.x, blockIdx.y, 0, A, Wh, (void*)out);
}

// ---------------------------------------------------------------------------
// Fused prep: X->fp16, W0..W3->fp16, RoPE table, zero dependency counters.
// ---------------------------------------------------------------------------
constexpr int XN4 = M_ * D_ / 4;
constexpr int WN4 = D_ * D_ / 4;
constexpr int PREP_N = XN4 + 4 * WN4 + L_ * 32;
constexpr int PREP_HALF = (PREP_N + 1) / 2;

__device__ __forceinline__ void prep_one(int i, const float4* __restrict__ X,
                                         const float4* __restrict__ W0,
                                         const float4* __restrict__ W1,
                                         const float4* __restrict__ W2,
                                         const float4* __restrict__ W3) {
    if (i < XN4) {
        const float4 v = X[i];
        __half2* o = (__half2*)g_Xh;
        o[2 * i]     = __floats2half2_rn(v.x, v.y);
        o[2 * i + 1] = __floats2half2_rn(v.z, v.w);
    } else if (i < XN4 + 4 * WN4) {
        const int widx = i - XN4;
        const int wi = widx >> 18, off = widx & (WN4 - 1);
        const float4* Wp = (wi == 0) ? W0 : (wi == 1) ? W1 : (wi == 2) ? W2 : W3;
        const float4 v = Wp[off];
        __half2* o = (__half2*)(g_Wh + (size_t)wi * D_ * D_);
        o[2 * off]     = __floats2half2_rn(v.x, v.y);
        o[2 * off + 1] = __floats2half2_rn(v.z, v.w);
    } else {
        const int r = i - XN4 - 4 * WN4;
        if (r < L_ * 32) {
            const int j = r & 31, l = r >> 5;
            const float invf = expf(-(float)j * 0.28782313662425575f);
            float s, c;
            sincosf((float)l * invf, &s, &c);
            g_cos[r] = c;
            g_sin[r] = s;
        }
    }
}

__global__ void prep_kernel(const float4* __restrict__ X,
                            const float4* __restrict__ W0, const float4* __restrict__ W1,
                            const float4* __restrict__ W2, const float4* __restrict__ W3) {
    const int i = blockIdx.x * blockDim.x + threadIdx.x;
    if (i < 3 * 64) g_cnt[i] = 0;           // zero dependency counters each run
    if (i >= PREP_HALF) return;
    prep_one(i, X, W0, W1, W2, W3);
    const int i2 = i + PREP_HALF;
    if (i2 < PREP_N) prep_one(i2, X, W0, W1, W2, W3);
}

// ---------------------------------------------------------------------------
extern "C" void kernel_launch(void* const* d_in, const int* in_sizes, int n_in,
                              void* d_out, int out_size) {
    const float* X = (const float*)d_in[0];
    float* out = (float*)d_out;

    __half *Sh, *Xh, *Wh;
    cudaGetSymbolAddress((void**)&Sh, g_Sh);
    cudaGetSymbolAddress((void**)&Xh, g_Xh);
    cudaGetSymbolAddress((void**)&Wh, g_Wh);

    cudaFuncSetAttribute(qkv_attn_fused, cudaFuncAttributeMaxDynamicSharedMemorySize, GSMEM);
    cudaFuncSetAttribute(gemm_o, cudaFuncAttributeMaxDynamicSharedMemorySize, GSMEM);

    prep_kernel<<<(PREP_HALF + 255) / 256, 256>>>((const float4*)X,
                                                  (const float4*)d_in[1], (const float4*)d_in[2],
                                                  (const float4*)d_in[3], (const float4*)d_in[4]);

    qkv_attn_fused<<<N_GEMM_CTAS + N_ATTN_CTAS, 256, GSMEM>>>(Xh, Wh);

    gemm_o<<<dim3(D_ / TN, M_ / TM), 256, GSMEM>>>(Sh, Wh + 3 * (size_t)D_ * D_, out);
}

// round 16
// speedup vs baseline: 1.0606x; 1.0275x over previous
#include <cuda_runtime.h>
#include <cuda_fp16.h>
#include <math.h>
#include <stdint.h>

// Problem constants
constexpr int B_ = 4, L_ = 2048, D_ = 1024, H_ = 16, HD_ = 64;
constexpr int M_ = B_ * L_;
constexpr int WINDOW_ = 128;
constexpr size_t HSZ = (size_t)B_ * H_ * L_ * HD_;

// GEMM tiling (R12 config — proven fastest)
constexpr int TM = 128, TN = 128, KS = 64;
constexpr int NK2 = D_ / KS;
constexpr int ROWB = 144;
constexpr int TILE_B = 128 * ROWB;
constexpr int STAGE_B = 2 * TILE_B;
constexpr int NSTG = 3;
constexpr int GSMEM = NSTG * STAGE_B;       // 110592

// Attention tiling: AQ=128 queries, 256-key window, streaming online softmax
constexpr int AQ = 128;
constexpr int ANK = 256;
constexpr int ASTR = 144;
constexpr int OFF_Q = 0;
constexpr int OFF_K = OFF_Q + AQ * ASTR;    // 18432
constexpr int OFF_V = OFF_K + ANK * ASTR;   // 55296

// Fused grid: 1536 QKV GEMM + 1024 attention + 512 O-proj CTAs
constexpr int N_GEMM_CTAS = 1536;
constexpr int N_ATTN_CTAS = (L_ / AQ) * (B_ * H_);   // 1024
constexpr int N_O_CTAS = 8 * 64;                      // 512
constexpr int ATTN_BASE = N_GEMM_CTAS;
constexpr int O_BASE = N_GEMM_CTAS + N_ATTN_CTAS;    // 2560

// Scratch (device globals)
__device__ __half g_QKVh[3 * HSZ];
__device__ __half g_Sh[(size_t)M_ * D_];
__device__ __half g_Xh[(size_t)M_ * D_];
__device__ __half g_Wh[4ull * D_ * D_];
__device__ float g_cos[L_ * 32];
__device__ float g_sin[L_ * 32];
__device__ int g_cntA[3 * 64];              // QKV completion per (z, row-block)
__device__ int g_cntB[64];                  // attention completion per row-block

__device__ __forceinline__ uint32_t smem_u32(const void* p) {
    uint32_t a;
    asm("{ .reg .u64 t; cvta.to.shared.u64 t, %1; cvt.u32.u64 %0, t; }" : "=r"(a) : "l"(p));
    return a;
}

#define LDSM4(r, addr) \
    asm volatile("ldmatrix.sync.aligned.m8n8.x4.shared.b16 {%0,%1,%2,%3}, [%4];" \
                 : "=r"((r)[0]), "=r"((r)[1]), "=r"((r)[2]), "=r"((r)[3]) : "r"(addr))

#define LDSM4T(r, addr) \
    asm volatile("ldmatrix.sync.aligned.m8n8.x4.trans.shared.b16 {%0,%1,%2,%3}, [%4];" \
                 : "=r"((r)[0]), "=r"((r)[1]), "=r"((r)[2]), "=r"((r)[3]) : "r"(addr))

#define MMAH(d, a, b0, b1) \
    asm volatile("mma.sync.aligned.m16n8k16.row.col.f32.f16.f16.f32 " \
                 "{%0,%1,%2,%3}, {%4,%5,%6,%7}, {%8,%9}, {%0,%1,%2,%3};" \
                 : "+f"((d)[0]), "+f"((d)[1]), "+f"((d)[2]), "+f"((d)[3]) \
                 : "r"((a)[0]), "r"((a)[1]), "r"((a)[2]), "r"((a)[3]), "r"(b0), "r"(b1))

#define CP_WAIT(n) asm volatile("cp.async.wait_group %0;" :: "n"(n) : "memory")

__device__ __forceinline__ void cp16(uint32_t sa, const void* g) {
    asm volatile("cp.async.cg.shared.global [%0], [%1], 16;" :: "r"(sa), "l"(g));
}

__device__ __forceinline__ uint32_t pack_h2(float lo, float hi) {
    __half2 h = __floats2half2_rn(lo, hi);
    return *(uint32_t*)&h;
}

__device__ __forceinline__ void cp_stage(char* st, const __half* a, const __half* wt,
                                         int ko, int tid) {
    const __half* gp[2] = {a, wt};
    const uint32_t sb = smem_u32(st);
#pragma unroll
    for (int t = 0; t < 2; t++) {
#pragma unroll
        for (int rep = 0; rep < 4; rep++) {
            const int c = rep * 256 + tid;
            const int row = c >> 3, ch = c & 7;
            cp16(sb + t * TILE_B + row * ROWB + ch * 16,
                 gp[t] + (size_t)row * D_ + ko + ch * 8);
        }
    }
    asm volatile("cp.async.commit_group;" ::: "memory");
}

// ---------------------------------------------------------------------------
// GEMM mainloop body (R12 config). MODE 0: fp32 row-major. MODE 1: fp16
// head-scatter.
// ---------------------------------------------------------------------------
template <int MODE>
__device__ __forceinline__ void gemm_body(char* sm, int xb, int yb, int z,
                                          const __half* __restrict__ A,
                                          const __half* __restrict__ Wh,
                                          void* __restrict__ outv) {
    const int tid = threadIdx.x;
    const int lane = tid & 31, wid = tid >> 5;
    const int mw = wid & 1, nw = wid >> 1;
    const int r0 = yb * TM, n0 = xb * TN;

    const __half* A_t = A + (size_t)r0 * D_;
    const __half* W_t = Wh + (size_t)z * D_ * D_ + (size_t)n0 * D_;

    float acc[4][4][4];
#pragma unroll
    for (int i = 0; i < 4; i++)
#pragma unroll
        for (int j = 0; j < 4; j++)
#pragma unroll
            for (int k = 0; k < 4; k++) acc[i][j][k] = 0.f;

    cp_stage(sm + 0 * STAGE_B, A_t, W_t, 0 * KS, tid);
    cp_stage(sm + 1 * STAGE_B, A_t, W_t, 1 * KS, tid);

    const uint32_t lrow = (lane & 15);
    const uint32_t lh = (lane >> 4) * 16;
    const uint32_t arow = (mw * 64 + lrow) * ROWB + lh;
    const uint32_t brow = (nw * 32 + lrow) * ROWB + lh;

    for (int kc = 0; kc < NK2; kc++) {
        const int s = kc % NSTG;
        if (kc + 1 < NK2) { CP_WAIT(1); } else { CP_WAIT(0); }
        __syncthreads();

        const uint32_t sb = smem_u32(sm + s * STAGE_B);
        uint32_t Bb[2][2][4];
        uint32_t Ab[2][4];
        LDSM4(Bb[0][0], sb + TILE_B + brow);
        LDSM4(Bb[0][1], sb + TILE_B + brow + 16 * ROWB);
        LDSM4(Ab[0], sb + arow);

        if (kc + 2 < NK2)
            cp_stage(sm + ((kc + 2) % NSTG) * STAGE_B, A_t, W_t, (kc + 2) * KS, tid);

#pragma unroll
        for (int kt = 0; kt < 4; kt++) {
            const int bc = kt & 1;
            if (kt < 3) {
                LDSM4(Bb[bc ^ 1][0], sb + TILE_B + brow + (kt + 1) * 32);
                LDSM4(Bb[bc ^ 1][1], sb + TILE_B + brow + 16 * ROWB + (kt + 1) * 32);
            }
#pragma unroll
            for (int mt = 0; mt < 4; mt++) {
                const int ac = mt & 1;
                if (mt < 3) {
                    LDSM4(Ab[ac ^ 1], sb + arow + (mt + 1) * 16 * ROWB + kt * 32);
                } else if (kt < 3) {
                    LDSM4(Ab[ac ^ 1], sb + arow + (kt + 1) * 32);
                }
#pragma unroll
                for (int nt = 0; nt < 4; nt++)
                    MMAH(acc[mt][nt], Ab[ac],
                         Bb[bc][nt >> 1][nt & 1], Bb[bc][nt >> 1][(nt & 1) + 2]);
            }
        }
    }

#pragma unroll
    for (int mt = 0; mt < 4; mt++) {
#pragma unroll
        for (int nt = 0; nt < 4; nt++) {
            const int row = r0 + mw * 64 + mt * 16 + (lane >> 2);
            const int col = n0 + nw * 32 + nt * 8 + 2 * (lane & 3);
            if (MODE == 1) {
                __half* out = (__half*)outv + (size_t)z * HSZ;
                const int h = col >> 6, dd = col & 63;
                const int bb0 = row >> 11, l0 = row & (L_ - 1);
                const int r8 = row + 8;
                const int bb1 = r8 >> 11, l1 = r8 & (L_ - 1);
                *(__half2*)(out + (((size_t)bb0 * H_ + h) * L_ + l0) * HD_ + dd) =
                    __floats2half2_rn(acc[mt][nt][0], acc[mt][nt][1]);
                *(__half2*)(out + (((size_t)bb1 * H_ + h) * L_ + l1) * HD_ + dd) =
                    __floats2half2_rn(acc[mt][nt][2], acc[mt][nt][3]);
            } else {
                float* out = (float*)outv;
                *(float2*)(out + (size_t)row * D_ + col) =
                    make_float2(acc[mt][nt][0], acc[mt][nt][1]);
                *(float2*)(out + (size_t)(row + 8) * D_ + col) =
                    make_float2(acc[mt][nt][2], acc[mt][nt][3]);
            }
        }
    }
}

// ---------------------------------------------------------------------------
// Attention body (R12 streaming config).
// ---------------------------------------------------------------------------
__device__ __forceinline__ void attn_body(char* sm, int qt, int bh) {
    const uint32_t sb = smem_u32(sm);
    const int tid = threadIdx.x;
    const int lane = tid & 31, w = tid >> 5;
    const int q0 = qt * AQ;
    const int ks0 = q0 - (WINDOW_ - 1);
    const int jmin = (q0 < WINDOW_ - 1) ? (WINDOW_ - 1 - q0) : 0;

    const __half* Qg = g_QKVh + (size_t)bh * L_ * HD_ + (size_t)q0 * HD_;
    for (int idx = tid; idx < AQ * 8; idx += 256) {
        const int row = idx >> 3, d0 = (idx & 7) * 4;
        const __half* qp = Qg + (size_t)row * HD_ + d0;
        const uint2 ua = *(const uint2*)qp;
        const uint2 ub = *(const uint2*)(qp + 32);
        const __half2* ha = (const __half2*)&ua;
        const __half2* hb = (const __half2*)&ub;
        const float a[4] = {__low2float(ha[0]), __high2float(ha[0]),
                            __low2float(ha[1]), __high2float(ha[1])};
        const float b[4] = {__low2float(hb[0]), __high2float(hb[0]),
                            __low2float(hb[1]), __high2float(hb[1])};
        const float4 cc = *(const float4*)(g_cos + (q0 + row) * 32 + d0);
        const float4 ss = *(const float4*)(g_sin + (q0 + row) * 32 + d0);
        const float c[4] = {cc.x, cc.y, cc.z, cc.w};
        const float s[4] = {ss.x, ss.y, ss.z, ss.w};
        char* p = sm + OFF_Q + row * ASTR + d0 * 2;
#pragma unroll
        for (int e = 0; e < 4; e += 2) {
            *(__half2*)(p + e * 2) = __floats2half2_rn(a[e] * c[e] - b[e] * s[e],
                                                       a[e + 1] * c[e + 1] - b[e + 1] * s[e + 1]);
            *(__half2*)(p + 64 + e * 2) = __floats2half2_rn(b[e] * c[e] + a[e] * s[e],
                                                            b[e + 1] * c[e + 1] + a[e + 1] * s[e + 1]);
        }
    }
    const __half* Kg = g_QKVh + HSZ + (size_t)bh * L_ * HD_;
    for (int idx = tid; idx < ANK * 8; idx += 256) {
        const int row = idx >> 3, d0 = (idx & 7) * 4;
        const int kg = ks0 + row;
        char* p = sm + OFF_K + row * ASTR + d0 * 2;
        if (kg < 0 || kg >= L_) {
            *(uint2*)p = make_uint2(0, 0);
            *(uint2*)(p + 64) = make_uint2(0, 0);
            continue;
        }
        const __half* kp = Kg + (size_t)kg * HD_ + d0;
        const uint2 ua = *(const uint2*)kp;
        const uint2 ub = *(const uint2*)(kp + 32);
        const __half2* ha = (const __half2*)&ua;
        const __half2* hb = (const __half2*)&ub;
        const float a[4] = {__low2float(ha[0]), __high2float(ha[0]),
                            __low2float(ha[1]), __high2float(ha[1])};
        const float b[4] = {__low2float(hb[0]), __high2float(hb[0]),
                            __low2float(hb[1]), __high2float(hb[1])};
        const float4 cc = *(const float4*)(g_cos + kg * 32 + d0);
        const float4 ss = *(const float4*)(g_sin + kg * 32 + d0);
        const float c[4] = {cc.x, cc.y, cc.z, cc.w};
        const float s[4] = {ss.x, ss.y, ss.z, ss.w};
#pragma unroll
        for (int e = 0; e < 4; e += 2) {
            *(__half2*)(p + e * 2) = __floats2half2_rn(a[e] * c[e] - b[e] * s[e],
                                                       a[e + 1] * c[e + 1] - b[e + 1] * s[e + 1]);
            *(__half2*)(p + 64 + e * 2) = __floats2half2_rn(b[e] * c[e] + a[e] * s[e],
                                                            b[e + 1] * c[e + 1] + a[e + 1] * s[e + 1]);
        }
    }
    const __half* Vg = g_QKVh + 2 * HSZ + (size_t)bh * L_ * HD_;
    for (int idx = tid; idx < ANK * 8; idx += 256) {
        const int row = idx >> 3, c8 = idx & 7;
        const int kg = ks0 + row;
        uint4 v = make_uint4(0, 0, 0, 0);
        if (kg >= 0 && kg < L_) v = *(const uint4*)(Vg + (size_t)kg * HD_ + c8 * 8);
        *(uint4*)(sm + OFF_V + row * ASTR + c8 * 16) = v;
    }
    __syncthreads();

    const uint32_t lrow = (lane & 15);
    const uint32_t lh = (lane >> 4) * 16;
    const int rw = 16 * w;

    uint32_t aq[4][4];
#pragma unroll
    for (int kt = 0; kt < 4; kt++)
        LDSM4(aq[kt], sb + OFF_Q + (rw + lrow) * ASTR + kt * 32 + lh);

    const int nb0 = max(0, max(rw, jmin) >> 4);
    const int nb1 = min(15, (rw + 142) >> 4);

    const int i1 = rw + (lane >> 2);
    const int i2 = i1 + 8;
    const int cq = (lane & 3) * 2;
    constexpr float SCALE = 0.125f;

    float m1 = -1e30f, m2 = -1e30f, l1 = 0.f, l2 = 0.f;
    float oac[8][4];
#pragma unroll
    for (int f = 0; f < 8; f++)
#pragma unroll
        for (int k = 0; k < 4; k++) oac[f][k] = 0.f;

    for (int nb = nb0; nb <= nb1; nb++) {
        float sc[2][4];
#pragma unroll
        for (int f = 0; f < 2; f++)
#pragma unroll
            for (int k = 0; k < 4; k++) sc[f][k] = 0.f;
#pragma unroll
        for (int kt = 0; kt < 4; kt++) {
            uint32_t bk[4];
            LDSM4(bk, sb + OFF_K + (nb * 16 + lrow) * ASTR + kt * 32 + lh);
            MMAH(sc[0], aq[kt], bk[0], bk[2]);
            MMAH(sc[1], aq[kt], bk[1], bk[3]);
        }

        bool kk[2][4];
        float bm1 = -1e30f, bm2 = -1e30f;
#pragma unroll
        for (int f = 0; f < 2; f++) {
            const int j0 = nb * 16 + f * 8 + cq, j1 = j0 + 1;
            kk[f][0] = ((unsigned)(j0 - i1) < (unsigned)WINDOW_) && j0 >= jmin;
            kk[f][1] = ((unsigned)(j1 - i1) < (unsigned)WINDOW_) && j1 >= jmin;
            kk[f][2] = ((unsigned)(j0 - i2) < (unsigned)WINDOW_) && j0 >= jmin;
            kk[f][3] = ((unsigned)(j1 - i2) < (unsigned)WINDOW_) && j1 >= jmin;
            sc[f][0] = kk[f][0] ? sc[f][0] * SCALE : -1e30f;
            sc[f][1] = kk[f][1] ? sc[f][1] * SCALE : -1e30f;
            sc[f][2] = kk[f][2] ? sc[f][2] * SCALE : -1e30f;
            sc[f][3] = kk[f][3] ? sc[f][3] * SCALE : -1e30f;
            bm1 = fmaxf(bm1, fmaxf(sc[f][0], sc[f][1]));
            bm2 = fmaxf(bm2, fmaxf(sc[f][2], sc[f][3]));
        }
        bm1 = fmaxf(bm1, __shfl_xor_sync(0xffffffffu, bm1, 1));
        bm1 = fmaxf(bm1, __shfl_xor_sync(0xffffffffu, bm1, 2));
        bm2 = fmaxf(bm2, __shfl_xor_sync(0xffffffffu, bm2, 1));
        bm2 = fmaxf(bm2, __shfl_xor_sync(0xffffffffu, bm2, 2));

        const float M1 = fmaxf(m1, bm1), M2 = fmaxf(m2, bm2);
        const float r1 = __expf(m1 - M1), r2 = __expf(m2 - M2);
        l1 *= r1; l2 *= r2;
#pragma unroll
        for (int f = 0; f < 8; f++) {
            oac[f][0] *= r1; oac[f][1] *= r1;
            oac[f][2] *= r2; oac[f][3] *= r2;
        }

        uint32_t pa[4];
#pragma unroll
        for (int f = 0; f < 2; f++) {
            const float p0 = kk[f][0] ? __expf(sc[f][0] - M1) : 0.f;
            const float p1 = kk[f][1] ? __expf(sc[f][1] - M1) : 0.f;
            const float p2 = kk[f][2] ? __expf(sc[f][2] - M2) : 0.f;
            const float p3 = kk[f][3] ? __expf(sc[f][3] - M2) : 0.f;
            l1 += p0 + p1;
            l2 += p2 + p3;
            pa[2 * f]     = pack_h2(p0, p1);
            pa[2 * f + 1] = pack_h2(p2, p3);
        }

#pragma unroll
        for (int db = 0; db < 4; db++) {
            uint32_t bv[4];
            LDSM4T(bv, sb + OFF_V + (nb * 16 + lrow) * ASTR + db * 32 + lh);
            MMAH(oac[2 * db],     pa, bv[0], bv[1]);
            MMAH(oac[2 * db + 1], pa, bv[2], bv[3]);
        }

        m1 = M1; m2 = M2;
    }

    l1 += __shfl_xor_sync(0xffffffffu, l1, 1);
    l1 += __shfl_xor_sync(0xffffffffu, l1, 2);
    l2 += __shfl_xor_sync(0xffffffffu, l2, 1);
    l2 += __shfl_xor_sync(0xffffffffu, l2, 2);

    const float inv1 = 1.f / l1, inv2 = 1.f / l2;
    const int bb = bh >> 4, h = bh & (H_ - 1);
    const size_t off1 = ((size_t)bb * L_ + q0 + i1) * D_ + h * HD_;
    const size_t off2 = ((size_t)bb * L_ + q0 + i2) * D_ + h * HD_;
#pragma unroll
    for (int f = 0; f < 8; f++) {
        const int d0 = 8 * f + cq;
        *(__half2*)(g_Sh + off1 + d0) =
            __floats2half2_rn(oac[f][0] * inv1, oac[f][1] * inv1);
        *(__half2*)(g_Sh + off2 + d0) =
            __floats2half2_rn(oac[f][2] * inv2, oac[f][3] * inv2);
    }
}

// ---------------------------------------------------------------------------
// Fully fused: QKV GEMM -> attention -> O-projection, one launch.
// Flag-based dependencies; dispatch order guarantees forward progress.
// ---------------------------------------------------------------------------
__global__ void __launch_bounds__(256, 2) mha_fused(const __half* __restrict__ Xh,
                                                    const __half* __restrict__ Wh,
                                                    float* __restrict__ out) {
    extern __shared__ char sm[];
    const int b = blockIdx.x;
    if (b < N_GEMM_CTAS) {
        // --- QKV projection tile ---
        const int xb = b & 7, yb = (b >> 3) & 63, z = b >> 9;
        gemm_body<1>(sm, xb, yb, z, Xh, Wh, (void*)g_QKVh);
        __threadfence();
        __syncthreads();
        if (threadIdx.x == 0)
            atomicAdd(&g_cntA[z * 64 + yb], 1);
    } else if (b < O_BASE) {
        // --- attention tile ---
        const int ab = b - ATTN_BASE;
        const int qt = ab & 15, bh = ab >> 4;
        const int bb = bh >> 4;
        const int y1 = bb * 16 + qt;
        const int y0 = (qt > 0) ? (y1 - 1) : y1;
        if (threadIdx.x == 0) {
            volatile int* vc = g_cntA;
            for (;;) {
                const bool ok = vc[0 * 64 + y0] == 8 && vc[0 * 64 + y1] == 8 &&
                                vc[1 * 64 + y0] == 8 && vc[1 * 64 + y1] == 8 &&
                                vc[2 * 64 + y0] == 8 && vc[2 * 64 + y1] == 8;
                if (ok) break;
                __nanosleep(128);
            }
        }
        __syncthreads();
        attn_body(sm, qt, bh);
        __threadfence();
        __syncthreads();
        if (threadIdx.x == 0)
            atomicAdd(&g_cntB[y1], 1);
    } else {
        // --- O-projection tile ---
        const int ob = b - O_BASE;
        const int xb = ob & 7, yb = ob >> 3;
        if (threadIdx.x == 0) {
            volatile int* vc = g_cntB;
            while (vc[yb] != 16) __nanosleep(128);
        }
        __syncthreads();
        gemm_body<0>(sm, xb, yb, 0, g_Sh, Wh + 3 * (size_t)D_ * D_, (void*)out);
    }
}

// ---------------------------------------------------------------------------
// Fused prep: X->fp16, W0..W3->fp16, RoPE table, zero dependency counters.
// ---------------------------------------------------------------------------
constexpr int XN4 = M_ * D_ / 4;
constexpr int WN4 = D_ * D_ / 4;
constexpr int PREP_N = XN4 + 4 * WN4 + L_ * 32;
constexpr int PREP_HALF = (PREP_N + 1) / 2;

__device__ __forceinline__ void prep_one(int i, const float4* __restrict__ X,
                                         const float4* __restrict__ W0,
                                         const float4* __restrict__ W1,
                                         const float4* __restrict__ W2,
                                         const float4* __restrict__ W3) {
    if (i < XN4) {
        const float4 v = X[i];
        __half2* o = (__half2*)g_Xh;
        o[2 * i]     = __floats2half2_rn(v.x, v.y);
        o[2 * i + 1] = __floats2half2_rn(v.z, v.w);
    } else if (i < XN4 + 4 * WN4) {
        const int widx = i - XN4;
        const int wi = widx >> 18, off = widx & (WN4 - 1);
        const float4* Wp = (wi == 0) ? W0 : (wi == 1) ? W1 : (wi == 2) ? W2 : W3;
        const float4 v = Wp[off];
        __half2* o = (__half2*)(g_Wh + (size_t)wi * D_ * D_);
        o[2 * off]     = __floats2half2_rn(v.x, v.y);
        o[2 * off + 1] = __floats2half2_rn(v.z, v.w);
    } else {
        const int r = i - XN4 - 4 * WN4;
        if (r < L_ * 32) {
            const int j = r & 31, l = r >> 5;
            const float invf = expf(-(float)j * 0.28782313662425575f);
            float s, c;
            sincosf((float)l * invf, &s, &c);
            g_cos[r] = c;
            g_sin[r] = s;
        }
    }
}

__global__ void prep_kernel(const float4* __restrict__ X,
                            const float4* __restrict__ W0, const float4* __restrict__ W1,
                            const float4* __restrict__ W2, const float4* __restrict__ W3) {
    const int i = blockIdx.x * blockDim.x + threadIdx.x;
    if (i < 3 * 64) g_cntA[i] = 0;
    if (i < 64) g_cntB[i] = 0;
    if (i >= PREP_HALF) return;
    prep_one(i, X, W0, W1, W2, W3);
    const int i2 = i + PREP_HALF;
    if (i2 < PREP_N) prep_one(i2, X, W0, W1, W2, W3);
}

// ---------------------------------------------------------------------------
extern "C" void kernel_launch(void* const* d_in, const int* in_sizes, int n_in,
                              void* d_out, int out_size) {
    const float* X = (const float*)d_in[0];
    float* out = (float*)d_out;

    __half *Xh, *Wh;
    cudaGetSymbolAddress((void**)&Xh, g_Xh);
    cudaGetSymbolAddress((void**)&Wh, g_Wh);

    cudaFuncSetAttribute(mha_fused, cudaFuncAttributeMaxDynamicSharedMemorySize, GSMEM);

    prep_kernel<<<(PREP_HALF + 255) / 256, 256>>>((const float4*)X,
                                                  (const float4*)d_in[1], (const float4*)d_in[2],
                                                  (const float4*)d_in[3], (const float4*)d_in[4]);

    mha_fused<<<N_GEMM_CTAS + N_ATTN_CTAS + N_O_CTAS, 256, GSMEM>>>(Xh, Wh, out);
}